// round 1
// baseline (speedup 1.0000x reference)
#include <cuda_runtime.h>
#include <cuda_fp16.h>
#include <cstdint>

// ---------------------------------------------------------------------------
// BitNetLinear: out[M,N] = (x[M,K] @ (ternary(W)[N,K])^T) * scale + bias[N]
// M=8192, N=4096, K=4096 (fp32 in/out). Strategy: exact fp16 ternary weights,
// fp16 activations, fp32 accumulation via mma.sync.m16n8k16.
// ---------------------------------------------------------------------------

#define THRESH (2.0f / 3.0f)

#define BM 128
#define BN 128
#define BK 32
#define LDS (BK + 8)          // skewed smem leading dim (halves) -> conflict-free ldmatrix
#define NPARTIAL 1024

// Scratch (device globals: no allocation allowed in kernel_launch)
static __device__ double g_abs_partial[NPARTIAL];
static __device__ float  g_scale;
static __device__ __half g_q[4096u * 4096u];        // 32 MB  ternary weights fp16
static __device__ __half g_xh[8192u * 4096u];       // 64 MB  activations fp16

// ---------------------------------------------------------------------------
// PTX helpers
// ---------------------------------------------------------------------------
__device__ __forceinline__ uint32_t smem_u32(const void* p) {
    return (uint32_t)__cvta_generic_to_shared(p);
}

__device__ __forceinline__ void cp_async16(uint32_t s, const void* g) {
    asm volatile("cp.async.cg.shared.global [%0], [%1], 16;\n" :: "r"(s), "l"(g));
}

__device__ __forceinline__ void ldmatrix_x4(uint32_t r[4], uint32_t addr) {
    asm volatile("ldmatrix.sync.aligned.m8n8.x4.shared.b16 {%0,%1,%2,%3}, [%4];\n"
                 : "=r"(r[0]), "=r"(r[1]), "=r"(r[2]), "=r"(r[3]) : "r"(addr));
}

__device__ __forceinline__ void ldmatrix_x2(uint32_t r[2], uint32_t addr) {
    asm volatile("ldmatrix.sync.aligned.m8n8.x2.shared.b16 {%0,%1}, [%2];\n"
                 : "=r"(r[0]), "=r"(r[1]) : "r"(addr));
}

__device__ __forceinline__ void mma16816(float c[4], const uint32_t a[4], const uint32_t b[2]) {
    asm volatile(
        "mma.sync.aligned.m16n8k16.row.col.f32.f16.f16.f32 "
        "{%0,%1,%2,%3}, {%4,%5,%6,%7}, {%8,%9}, {%0,%1,%2,%3};\n"
        : "+f"(c[0]), "+f"(c[1]), "+f"(c[2]), "+f"(c[3])
        : "r"(a[0]), "r"(a[1]), "r"(a[2]), "r"(a[3]), "r"(b[0]), "r"(b[1]));
}

// ---------------------------------------------------------------------------
// Preprocessing kernels
// ---------------------------------------------------------------------------
__global__ void k_abs_partial(const float* __restrict__ w, int n) {
    double s = 0.0;
    for (int i = blockIdx.x * blockDim.x + threadIdx.x; i < n; i += gridDim.x * blockDim.x)
        s += (double)fabsf(w[i]);
    __shared__ double sm[256];
    sm[threadIdx.x] = s;
    __syncthreads();
    for (int o = 128; o > 0; o >>= 1) {
        if (threadIdx.x < o) sm[threadIdx.x] += sm[threadIdx.x + o];
        __syncthreads();
    }
    if (threadIdx.x == 0) g_abs_partial[blockIdx.x] = sm[0];
}

__global__ void k_scale(int n) {
    __shared__ double sm[256];
    double s = 0.0;
    for (int i = threadIdx.x; i < NPARTIAL; i += 256) s += g_abs_partial[i];
    sm[threadIdx.x] = s;
    __syncthreads();
    for (int o = 128; o > 0; o >>= 1) {
        if (threadIdx.x < o) sm[threadIdx.x] += sm[threadIdx.x + o];
        __syncthreads();
    }
    if (threadIdx.x == 0) {
        float sc = (float)(sm[0] / (double)n);
        sc = fminf(fmaxf(sc, 1e-5f), 1000.0f);
        g_scale = sc;
    }
}

__device__ __forceinline__ __half ternh(float v, float t) {
    float q = (v > t) ? 1.0f : ((v < -t) ? -1.0f : 0.0f);
    return __float2half_rn(q);
}

__global__ void k_quant(const float4* __restrict__ w4, int n4) {
    const float t = THRESH * g_scale;
    __half2* dst = reinterpret_cast<__half2*>(g_q);
    for (int i = blockIdx.x * blockDim.x + threadIdx.x; i < n4; i += gridDim.x * blockDim.x) {
        float4 v = w4[i];
        dst[2 * i + 0] = __halves2half2(ternh(v.x, t), ternh(v.y, t));
        dst[2 * i + 1] = __halves2half2(ternh(v.z, t), ternh(v.w, t));
    }
}

__global__ void k_xconv(const float4* __restrict__ x4, int n4) {
    __half2* dst = reinterpret_cast<__half2*>(g_xh);
    for (int i = blockIdx.x * blockDim.x + threadIdx.x; i < n4; i += gridDim.x * blockDim.x) {
        float4 v = x4[i];
        dst[2 * i + 0] = __halves2half2(__float2half_rn(v.x), __float2half_rn(v.y));
        dst[2 * i + 1] = __halves2half2(__float2half_rn(v.z), __float2half_rn(v.w));
    }
}

// ---------------------------------------------------------------------------
// GEMM: C[M,N] = A[M,K] * B[N,K]^T  (A=g_xh, B=g_q, fp16 in, fp32 accum)
// Block 128x128x32, 256 threads, 8 warps in 2(m) x 4(n); warp tile 64x32.
// Double-buffered cp.async pipeline.
// ---------------------------------------------------------------------------
__global__ void __launch_bounds__(256)
k_gemm(const float* __restrict__ bias, float* __restrict__ out,
       int M, int N, int K) {
    __shared__ __half As[2][BM * LDS];   // 2 * 10240 B
    __shared__ __half Bs[2][BN * LDS];   // 2 * 10240 B

    const int tid  = threadIdx.x;
    const int warp = tid >> 5;
    const int lane = tid & 31;
    const int wm = (warp & 1) * 64;      // warp row base within block tile
    const int wn = (warp >> 1) * 32;     // warp col base within block tile
    const int m0 = blockIdx.y * BM;
    const int n0 = blockIdx.x * BN;

    const __half* Ag = g_xh + (size_t)m0 * K;
    const __half* Bg = g_q  + (size_t)n0 * K;

    float acc[4][4][4];
#pragma unroll
    for (int i = 0; i < 4; i++)
#pragma unroll
        for (int j = 0; j < 4; j++)
#pragma unroll
            for (int l = 0; l < 4; l++) acc[i][j][l] = 0.0f;

    // 512 16B-chunks per tile (128 rows x 4 chunks), 2 per thread
    const int r0 = tid >> 2;           // chunk row (first half)
    const int c0 = (tid & 3) * 8;      // halves offset within row
    const int r1 = r0 + 64;

    auto load_stage = [&](int stage, int k0) {
        cp_async16(smem_u32(&As[stage][r0 * LDS + c0]), Ag + (size_t)r0 * K + k0 + c0);
        cp_async16(smem_u32(&As[stage][r1 * LDS + c0]), Ag + (size_t)r1 * K + k0 + c0);
        cp_async16(smem_u32(&Bs[stage][r0 * LDS + c0]), Bg + (size_t)r0 * K + k0 + c0);
        cp_async16(smem_u32(&Bs[stage][r1 * LDS + c0]), Bg + (size_t)r1 * K + k0 + c0);
    };

    const int NK = K / BK;
    load_stage(0, 0);
    asm volatile("cp.async.commit_group;\n");

    for (int kt = 0; kt < NK; ++kt) {
        const int cur = kt & 1;
        if (kt + 1 < NK) {
            load_stage(cur ^ 1, (kt + 1) * BK);
            asm volatile("cp.async.commit_group;\n");
            asm volatile("cp.async.wait_group 1;\n");
        } else {
            asm volatile("cp.async.wait_group 0;\n");
        }
        __syncthreads();

#pragma unroll
        for (int kk = 0; kk < BK; kk += 16) {
            uint32_t a[4][4], b[4][2];
#pragma unroll
            for (int mi = 0; mi < 4; ++mi) {
                int row = wm + mi * 16 + (lane & 15);
                int col = kk + (lane >> 4) * 8;
                ldmatrix_x4(a[mi], smem_u32(&As[cur][row * LDS + col]));
            }
#pragma unroll
            for (int ni = 0; ni < 4; ++ni) {
                int r = lane & 15;
                int row = wn + ni * 8 + (r & 7);
                int col = kk + (r >> 3) * 8;
                ldmatrix_x2(b[ni], smem_u32(&Bs[cur][row * LDS + col]));
            }
#pragma unroll
            for (int mi = 0; mi < 4; ++mi)
#pragma unroll
                for (int ni = 0; ni < 4; ++ni)
                    mma16816(acc[mi][ni], a[mi], b[ni]);
        }
        __syncthreads();
    }

    // Epilogue: out = acc * scale + bias
    const float scale = g_scale;
#pragma unroll
    for (int mi = 0; mi < 4; ++mi) {
#pragma unroll
        for (int ni = 0; ni < 4; ++ni) {
            int row = m0 + wm + mi * 16 + (lane >> 2);
            int col = n0 + wn + ni * 8 + (lane & 3) * 2;
            float b0 = bias[col], b1 = bias[col + 1];
            float2 v0, v1;
            v0.x = acc[mi][ni][0] * scale + b0;
            v0.y = acc[mi][ni][1] * scale + b1;
            v1.x = acc[mi][ni][2] * scale + b0;
            v1.y = acc[mi][ni][3] * scale + b1;
            *reinterpret_cast<float2*>(out + (size_t)row * N + col)       = v0;
            *reinterpret_cast<float2*>(out + (size_t)(row + 8) * N + col) = v1;
        }
    }
}

// ---------------------------------------------------------------------------
// Launch
// ---------------------------------------------------------------------------
extern "C" void kernel_launch(void* const* d_in, const int* in_sizes, int n_in,
                              void* d_out, int out_size) {
    const float* x    = (const float*)d_in[0];
    const float* w    = (const float*)d_in[1];
    const float* bias = (const float*)d_in[2];
    float* out = (float*)d_out;

    const int N = in_sizes[2];            // 4096
    const int K = in_sizes[1] / N;        // 4096
    const int M = in_sizes[0] / K;        // 8192
    const int nw = in_sizes[1];
    const int nx = in_sizes[0];

    k_abs_partial<<<NPARTIAL, 256>>>(w, nw);
    k_scale<<<1, 256>>>(nw);
    k_quant<<<2048, 256>>>((const float4*)w, nw / 4);
    k_xconv<<<4096, 256>>>((const float4*)x, nx / 4);

    dim3 grid(N / BN, M / BM);
    k_gemm<<<grid, 256>>>(bias, out, M, N, K);
}

// round 3
// speedup vs baseline: 1.0787x; 1.0787x over previous
#include <cuda_runtime.h>
#include <cuda_fp16.h>
#include <cstdint>

// ---------------------------------------------------------------------------
// BitNetLinear: out[M,N] = (x[M,K] @ ternary(W)[N,K]^T) * scale + bias[N]
// M=8192, N=4096, K=4096. fp16 operands (ternary exact), fp32 accum,
// legacy mma.sync.m16n8k16 (tcgen05 not available: harness targets sm_103
// without the 'a' feature set).
// Block 128x128x32, 256 threads (8 warps, 2x4, warp tile 64x32),
// 4-stage cp.async pipeline, one barrier per k-iteration, 2 CTAs/SM.
// ---------------------------------------------------------------------------

#define THRESH (2.0f / 3.0f)

#define BM 128
#define BN 128
#define BK 32
#define LDS (BK + 8)          // skewed leading dim in halves -> conflict-free
#define STAGES 4
#define NPARTIAL 1024

#define A_STAGE (BM * LDS)    // halves
#define B_STAGE (BN * LDS)

// Scratch (device globals: no allocation allowed)
static __device__ double g_abs_partial[NPARTIAL];
static __device__ float  g_scale;
static __device__ __half g_q[4096u * 4096u];        // 32 MB ternary weights fp16
static __device__ __half g_xh[8192u * 4096u];       // 64 MB activations fp16

// ---------------------------------------------------------------------------
// PTX helpers
// ---------------------------------------------------------------------------
__device__ __forceinline__ uint32_t smem_u32(const void* p) {
    return (uint32_t)__cvta_generic_to_shared(p);
}

__device__ __forceinline__ void cp_async16(uint32_t s, const void* g) {
    asm volatile("cp.async.cg.shared.global [%0], [%1], 16;\n" :: "r"(s), "l"(g));
}

__device__ __forceinline__ void ldmatrix_x4(uint32_t r[4], uint32_t addr) {
    asm volatile("ldmatrix.sync.aligned.m8n8.x4.shared.b16 {%0,%1,%2,%3}, [%4];\n"
                 : "=r"(r[0]), "=r"(r[1]), "=r"(r[2]), "=r"(r[3]) : "r"(addr));
}

__device__ __forceinline__ void mma16816(float c[4], const uint32_t a[4], const uint32_t b[2]) {
    asm volatile(
        "mma.sync.aligned.m16n8k16.row.col.f32.f16.f16.f32 "
        "{%0,%1,%2,%3}, {%4,%5,%6,%7}, {%8,%9}, {%0,%1,%2,%3};\n"
        : "+f"(c[0]), "+f"(c[1]), "+f"(c[2]), "+f"(c[3])
        : "r"(a[0]), "r"(a[1]), "r"(a[2]), "r"(a[3]), "r"(b[0]), "r"(b[1]));
}

// ---------------------------------------------------------------------------
// Preprocessing
// ---------------------------------------------------------------------------
__global__ void k_abs_partial(const float* __restrict__ w, int n) {
    double s = 0.0;
    for (int i = blockIdx.x * blockDim.x + threadIdx.x; i < n; i += gridDim.x * blockDim.x)
        s += (double)fabsf(w[i]);
    __shared__ double sm[256];
    sm[threadIdx.x] = s;
    __syncthreads();
    for (int o = 128; o > 0; o >>= 1) {
        if (threadIdx.x < o) sm[threadIdx.x] += sm[threadIdx.x + o];
        __syncthreads();
    }
    if (threadIdx.x == 0) g_abs_partial[blockIdx.x] = sm[0];
}

__global__ void k_scale(int n) {
    __shared__ double sm[256];
    double s = 0.0;
    for (int i = threadIdx.x; i < NPARTIAL; i += 256) s += g_abs_partial[i];
    sm[threadIdx.x] = s;
    __syncthreads();
    for (int o = 128; o > 0; o >>= 1) {
        if (threadIdx.x < o) sm[threadIdx.x] += sm[threadIdx.x + o];
        __syncthreads();
    }
    if (threadIdx.x == 0) {
        float sc = (float)(sm[0] / (double)n);
        g_scale = fminf(fmaxf(sc, 1e-5f), 1000.0f);
    }
}

__device__ __forceinline__ __half ternh(float v, float t) {
    float q = (v > t) ? 1.0f : ((v < -t) ? -1.0f : 0.0f);
    return __float2half_rn(q);
}

__global__ void k_quant(const float4* __restrict__ w4, int n4) {
    const float t = THRESH * g_scale;
    __half2* dst = reinterpret_cast<__half2*>(g_q);
    for (int i = blockIdx.x * blockDim.x + threadIdx.x; i < n4; i += gridDim.x * blockDim.x) {
        float4 v = w4[i];
        dst[2 * i + 0] = __halves2half2(ternh(v.x, t), ternh(v.y, t));
        dst[2 * i + 1] = __halves2half2(ternh(v.z, t), ternh(v.w, t));
    }
}

__global__ void k_xconv(const float4* __restrict__ x4, int n4) {
    __half2* dst = reinterpret_cast<__half2*>(g_xh);
    for (int i = blockIdx.x * blockDim.x + threadIdx.x; i < n4; i += gridDim.x * blockDim.x) {
        float4 v = x4[i];
        dst[2 * i + 0] = __halves2half2(__float2half_rn(v.x), __float2half_rn(v.y));
        dst[2 * i + 1] = __halves2half2(__float2half_rn(v.z), __float2half_rn(v.w));
    }
}

// ---------------------------------------------------------------------------
// GEMM: C = A * B^T, A=g_xh [M,K], B=g_q [N,K], fp16 -> fp32
// ---------------------------------------------------------------------------
__global__ void __launch_bounds__(256, 2)
k_gemm(const float* __restrict__ bias, float* __restrict__ out,
       int M, int N, int K) {
    extern __shared__ __half smem[];
    __half* As = smem;                       // STAGES * A_STAGE halves
    __half* Bs = smem + STAGES * A_STAGE;    // STAGES * B_STAGE halves

    const int tid  = threadIdx.x;
    const int warp = tid >> 5;
    const int lane = tid & 31;
    const int wm = (warp & 1) * 64;
    const int wn = (warp >> 1) * 32;
    const int m0 = blockIdx.y * BM;
    const int n0 = blockIdx.x * BN;

    const __half* Ag = g_xh + (size_t)m0 * K;
    const __half* Bg = g_q  + (size_t)n0 * K;

    float acc[4][4][4];
#pragma unroll
    for (int i = 0; i < 4; i++)
#pragma unroll
        for (int j = 0; j < 4; j++)
#pragma unroll
            for (int l = 0; l < 4; l++) acc[i][j][l] = 0.0f;

    // per-stage: 128 rows x 4 16B-chunks each for A and B; 2 chunks/thread each
    const int r0 = tid >> 2;
    const int c0 = (tid & 3) * 8;
    const int r1 = r0 + 64;

    auto load_stage = [&](int stage, int k0) {
        __half* as = As + stage * A_STAGE;
        __half* bs = Bs + stage * B_STAGE;
        cp_async16(smem_u32(&as[r0 * LDS + c0]), Ag + (size_t)r0 * K + k0 + c0);
        cp_async16(smem_u32(&as[r1 * LDS + c0]), Ag + (size_t)r1 * K + k0 + c0);
        cp_async16(smem_u32(&bs[r0 * LDS + c0]), Bg + (size_t)r0 * K + k0 + c0);
        cp_async16(smem_u32(&bs[r1 * LDS + c0]), Bg + (size_t)r1 * K + k0 + c0);
        asm volatile("cp.async.commit_group;\n");
    };

    const int NK = K / BK;   // 128
#pragma unroll
    for (int s = 0; s < STAGES - 1; s++) load_stage(s, s * BK);

    // ldmatrix source addresses (stage-invariant offsets)
    const int a_row = (lane & 15);
    const int a_col = (lane >> 4) * 8;
    const int b_row = ((lane >> 4) & 1) * 8 + (lane & 7);   // n offset within 16
    const int b_col = ((lane >> 3) & 1) * 8;                // k offset within 16

    for (int kt = 0; kt < NK; ++kt) {
        const int cur = kt & (STAGES - 1);
        asm volatile("cp.async.wait_group %0;\n" :: "n"(STAGES - 2));
        __syncthreads();

        if (kt + STAGES - 1 < NK)
            load_stage((kt + STAGES - 1) & (STAGES - 1), (kt + STAGES - 1) * BK);

        const __half* as = As + cur * A_STAGE;
        const __half* bs = Bs + cur * B_STAGE;

#pragma unroll
        for (int kk = 0; kk < BK; kk += 16) {
            uint32_t a[4][4], b[4][2];
#pragma unroll
            for (int mi = 0; mi < 4; ++mi)
                ldmatrix_x4(a[mi],
                    smem_u32(&as[(wm + mi * 16 + a_row) * LDS + kk + a_col]));
#pragma unroll
            for (int ni = 0; ni < 4; ni += 2) {
                uint32_t r[4];
                ldmatrix_x4(r,
                    smem_u32(&bs[(wn + ni * 8 + b_row) * LDS + kk + b_col]));
                b[ni][0] = r[0]; b[ni][1] = r[1];
                b[ni + 1][0] = r[2]; b[ni + 1][1] = r[3];
            }
#pragma unroll
            for (int mi = 0; mi < 4; ++mi)
#pragma unroll
                for (int ni = 0; ni < 4; ++ni)
                    mma16816(acc[mi][ni], a[mi], b[ni]);
        }
    }

    // Epilogue: out = acc * scale + bias
    const float scale = g_scale;
#pragma unroll
    for (int mi = 0; mi < 4; ++mi) {
#pragma unroll
        for (int ni = 0; ni < 4; ++ni) {
            int row = m0 + wm + mi * 16 + (lane >> 2);
            int col = n0 + wn + ni * 8 + (lane & 3) * 2;
            float b0 = bias[col], b1 = bias[col + 1];
            float2 v0, v1;
            v0.x = acc[mi][ni][0] * scale + b0;
            v0.y = acc[mi][ni][1] * scale + b1;
            v1.x = acc[mi][ni][2] * scale + b0;
            v1.y = acc[mi][ni][3] * scale + b1;
            *reinterpret_cast<float2*>(out + (size_t)row * N + col)       = v0;
            *reinterpret_cast<float2*>(out + (size_t)(row + 8) * N + col) = v1;
        }
    }
}

// ---------------------------------------------------------------------------
// Launch
// ---------------------------------------------------------------------------
extern "C" void kernel_launch(void* const* d_in, const int* in_sizes, int n_in,
                              void* d_out, int out_size) {
    const float* x    = (const float*)d_in[0];
    const float* w    = (const float*)d_in[1];
    const float* bias = (const float*)d_in[2];
    float* out = (float*)d_out;

    const int N = in_sizes[2];            // 4096
    const int K = in_sizes[1] / N;        // 4096
    const int M = in_sizes[0] / K;        // 8192
    const int nw = in_sizes[1];
    const int nx = in_sizes[0];

    k_abs_partial<<<NPARTIAL, 256>>>(w, nw);
    k_scale<<<1, 256>>>(nw);
    k_quant<<<2048, 256>>>((const float4*)w, nw / 4);
    k_xconv<<<4096, 256>>>((const float4*)x, nx / 4);

    const int smem_bytes = STAGES * (A_STAGE + B_STAGE) * (int)sizeof(__half); // 81920
    cudaFuncSetAttribute(k_gemm, cudaFuncAttributeMaxDynamicSharedMemorySize,
                         smem_bytes);
    dim3 grid(N / BN, M / BM);
    k_gemm<<<grid, 256, smem_bytes>>>(bias, out, M, N, K);
}